// round 15
// baseline (speedup 1.0000x reference)
#include <cuda_runtime.h>
#include <cstdint>

// NAF layer: A = -0.5 * d^T (L L^T) d  ==  -0.5 * ||L^T d||^2
// L lower-triangular, packed row-major (tril order): (i,j) at i*(i+1)/2 + j.
// Diagonal entries exp(x)+eps, off-diagonal raw.
//
// R13 lesson: both persistent variants regressed (addressing ALU + scattered
// footprint). Reverting to R11's proven structure (launch-per-row, 3 chunked
// cp.async commit groups, consume-as-it-lands) with ONE change: WPB=1 — one
// warp = one block = one row. Same 24 warps/SM (24 blocks x 8320B = 200KB),
// but 4x shorter block duration -> finer CLC backfill, smaller end drain.
// Lane l owns columns j=l and j=l+32.

#define NB_ACTIONS 64
#define NB_ELEMS   2080            // 520 float4 per row
#define EPSV       1e-7f
#define TRI(i) ((i) * ((i) + 1) / 2)

// chunk boundaries in float4 units (floats: 0..527 | 528..1175 | 1176..2079)
#define F4_A   132                 // TRI(32)/4
#define F4_B   294                 // TRI(48)/4
#define F4_C   520                 // TRI(64)/4

#define CPA(dst, src) \
    asm volatile("cp.async.cg.shared.global [%0], [%1], 16;\n" \
                 :: "r"(dst), "l"(src))

__global__ __launch_bounds__(32, 24)
void naf_kernel(const float* __restrict__ Lf,
                const float* __restrict__ mu,
                const float* __restrict__ a,
                float* __restrict__ out,
                int B)
{
    __shared__ float sw[NB_ELEMS];   // 8320 B/block

    const int lane = threadIdx.x;    // 32-thread block == one warp
    const int row  = blockIdx.x;
    if (row >= B) return;

    // ---- Stage row global -> shared in 3 cp.async commit groups ----
    {
        const float4* __restrict__ src =
            (const float4*)(Lf + (size_t)row * NB_ELEMS);
        const unsigned int sdst = (unsigned int)__cvta_generic_to_shared(sw);

        // group A: f4 [0, 132)  -> rows 0..31
        #pragma unroll
        for (int it = 0; it < 5; ++it) {
            const int idx = it * 32 + lane;
            if (idx < F4_A) CPA(sdst + idx * 16, src + idx);
        }
        asm volatile("cp.async.commit_group;\n");

        // group B: f4 [132, 294) -> rows 32..47
        #pragma unroll
        for (int it = 0; it < 6; ++it) {
            const int idx = F4_A + it * 32 + lane;
            if (idx < F4_B) CPA(sdst + idx * 16, src + idx);
        }
        asm volatile("cp.async.commit_group;\n");

        // group C: f4 [294, 520) -> rows 48..63
        #pragma unroll
        for (int it = 0; it < 8; ++it) {
            const int idx = F4_B + it * 32 + lane;
            if (idx < F4_C) CPA(sdst + idx * 16, src + idx);
        }
        asm volatile("cp.async.commit_group;\n");
    }

    // d-vector loads in flight before any wait
    const size_t vb = (size_t)row * NB_ACTIONS;
    const int j1 = lane + 32;
    const float a0 = a[vb + lane], m0 = mu[vb + lane];
    const float a1 = a[vb + j1],   m1 = mu[vb + j1];

    const float dlo = a0 - m0;   // d[lane]
    const float dhi = a1 - m1;   // d[lane+32]

    float y0 = 0.0f;   // column j = lane
    float y1 = 0.0f;   // column j = lane + 32

    // ---- Chunk A ready: rows 0..31 (y0 only; diag raw, corrected later) ----
    asm volatile("cp.async.wait_group 2;\n" ::: "memory");
    __syncwarp();

    const float diagRaw0 = sw[TRI(lane) + lane];   // in chunk A
    #pragma unroll
    for (int i = 0; i < 32; ++i) {
        const float v  = sw[TRI(i) + lane];        // conflict-free LDS
        const float di = __shfl_sync(0xffffffffu, dlo, i);
        const float m  = (lane <= i) ? di : 0.0f;
        y0 = fmaf(v, m, y0);
    }

    // ---- Chunk B ready: rows 32..47 ----
    asm volatile("cp.async.wait_group 1;\n" ::: "memory");
    __syncwarp();

    #pragma unroll
    for (int i = 32; i < 48; ++i) {
        const int t = TRI(i);
        const float vlo = sw[t + lane];
        const float vhi = sw[t + j1];
        const float di  = __shfl_sync(0xffffffffu, dhi, i - 32);
        y0 = fmaf(vlo, di, y0);
        const float m = (j1 <= i) ? di : 0.0f;
        y1 = fmaf(vhi, m, y1);
    }

    // ---- Chunk C ready: rows 48..63 ----
    asm volatile("cp.async.wait_group 0;\n" ::: "memory");
    __syncwarp();

    #pragma unroll
    for (int i = 48; i < 64; ++i) {
        const int t = TRI(i);
        const float vlo = sw[t + lane];
        const float vhi = sw[t + j1];
        const float di  = __shfl_sync(0xffffffffu, dhi, i - 32);
        y0 = fmaf(vlo, di, y0);
        const float m = (j1 <= i) ? di : 0.0f;
        y1 = fmaf(vhi, m, y1);
    }

    // Diagonal correction: loops added raw*d_self; want (exp(raw)+eps)*d_self.
    const float diagRaw1 = sw[TRI(j1) + j1];
    y0 = fmaf(expf(diagRaw0) + EPSV - diagRaw0, dlo, y0);
    y1 = fmaf(expf(diagRaw1) + EPSV - diagRaw1, dhi, y1);

    // quad = sum_j y_j^2 ; butterfly warp reduction
    float q = fmaf(y0, y0, y1 * y1);
    #pragma unroll
    for (int off = 16; off; off >>= 1)
        q += __shfl_xor_sync(0xffffffffu, q, off);

    if (lane == 0) out[row] = -0.5f * q;
}

extern "C" void kernel_launch(void* const* d_in, const int* in_sizes, int n_in,
                              void* d_out, int out_size)
{
    const float* Lf = (const float*)d_in[0];   // [B, 2080]
    const float* mu = (const float*)d_in[1];   // [B, 64]
    const float* a  = (const float*)d_in[2];   // [B, 64]
    float* out = (float*)d_out;                // [B, 1]

    const int B = in_sizes[0] / NB_ELEMS;

    naf_kernel<<<B, 32>>>(Lf, mu, a, out, B);  // one warp-block per row
}